// round 1
// baseline (speedup 1.0000x reference)
#include <cuda_runtime.h>

// Local Scale Attention, fused fp32 implementation (round 1 baseline).
// B=2048, N=84 tokens, C=256, H=8 heads, hd=32.
//
// Kernel 1: gather relative-position bias into g_bias[h][q][k].
// Kernel 2: per-batch fused QKV + attention, writes g_attn[b][n][c].
// Kernel 3: output projection GEMM, writes d_out.
//
// All heavy math uses packed fma.rn.f32x2 (2 fp32 FMA / instr) since plain
// FFMA on sm_103a is half-rate (rt_SMSP=2).

#define BATCH 2048
#define NTOK  84
#define DIM   256
#define HEADS 8

typedef unsigned long long u64;

__device__ float g_attn[(size_t)BATCH * NTOK * DIM];   // 176 MB scratch
__device__ float g_bias[HEADS * NTOK * NTOK];

__device__ __forceinline__ u64 ffma2(u64 a, u64 b, u64 c) {
    u64 d;
    asm("fma.rn.f32x2 %0, %1, %2, %3;" : "=l"(d) : "l"(a), "l"(b), "l"(c));
    return d;
}
__device__ __forceinline__ float hsum2(u64 v) {
    float lo, hi;
    asm("mov.b64 {%0, %1}, %2;" : "=f"(lo), "=f"(hi) : "l"(v));
    return lo + hi;
}

// ---------------------------------------------------------------------------
// Kernel 1: bias gather. g_bias[h*7056 + q*84 + k] = table[ridx[q*84+k]*8 + h]
// ---------------------------------------------------------------------------
__global__ void bias_kernel(const float* __restrict__ table, const int* __restrict__ ridx)
{
    int i = blockIdx.x * blockDim.x + threadIdx.x;
    if (i < NTOK * NTOK) {
        int r = ridx[i];
        #pragma unroll
        for (int h = 0; h < HEADS; ++h)
            g_bias[h * (NTOK * NTOK) + i] = table[r * HEADS + h];
    }
}

// ---------------------------------------------------------------------------
// Kernel 2: fused QKV projection + attention per batch element.
// smem layout (floats):
//   xs : [88][256]      = 22528   (rows 84..87 uninitialized, never stored)
//   ws : [96][68]       =  6528   (transposed W slice, 64-deep K tile, pad 68)
//   sQ : [88][36]       =  3168
//   sK : [88][36]       =  3168
//   sV : [88][36]       =  3168
//   sS : [88][88]       =  7744
// total 46304 floats = 185216 bytes
// ---------------------------------------------------------------------------
__global__ __launch_bounds__(256, 1)
void attn_kernel(const float* __restrict__ x,
                 const float* __restrict__ Wqkv,
                 const float* __restrict__ bqkv)
{
    extern __shared__ float sm[];
    float* xs = sm;
    float* ws = sm + 22528;
    float* sQ = sm + 29056;
    float* sK = sm + 32224;
    float* sV = sm + 35392;
    float* sS = sm + 38560;

    const int tid = threadIdx.x;
    const int w = tid >> 5, l = tid & 31;
    const int b = blockIdx.x;
    const float scale = 0.10910894511799618f;   // 84^-0.5

    // ---- load x[b] tile (84x256) ----
    {
        const float4* xg = reinterpret_cast<const float4*>(x + (size_t)b * (NTOK * DIM));
        float4* xs4 = reinterpret_cast<float4*>(xs);
        #pragma unroll
        for (int i = 0; i < 21; ++i)          // 21*256 = 5376 float4 = 84*256 floats
            xs4[tid + 256 * i] = xg[tid + 256 * i];
    }

    for (int h = 0; h < HEADS; ++h) {
        // ================= QKV GEMM for head h =================
        // thread (w,l) owns rows {w+8i, i<11}, cols: q[l], k[l], v[l]
        u64 acc[11][3];
        #pragma unroll
        for (int i = 0; i < 11; ++i) {
            acc[i][0] = 0ull; acc[i][1] = 0ull; acc[i][2] = 0ull;
        }

        for (int kt = 0; kt < 4; ++kt) {
            __syncthreads();   // also covers xs-load (first iter) and prior-head smem reuse
            // stage ws[j][kk] = Wqkv[kt*64+kk][(j/32)*256 + h*32 + (j%32)]
            for (int idx = tid; idx < 96 * 64; idx += 256) {
                int j = idx % 96, kk = idx / 96;
                ws[j * 68 + kk] =
                    Wqkv[(kt * 64 + kk) * 768 + (j >> 5) * 256 + h * 32 + (j & 31)];
            }
            __syncthreads();
            #pragma unroll 4
            for (int kk4 = 0; kk4 < 16; ++kk4) {
                ulonglong2 wv0 = *reinterpret_cast<const ulonglong2*>(&ws[ l       * 68 + kk4 * 4]);
                ulonglong2 wv1 = *reinterpret_cast<const ulonglong2*>(&ws[(l + 32) * 68 + kk4 * 4]);
                ulonglong2 wv2 = *reinterpret_cast<const ulonglong2*>(&ws[(l + 64) * 68 + kk4 * 4]);
                #pragma unroll
                for (int i = 0; i < 11; ++i) {
                    int row = w + 8 * i;
                    ulonglong2 xv = *reinterpret_cast<const ulonglong2*>(
                        &xs[row * 256 + kt * 64 + kk4 * 4]);
                    acc[i][0] = ffma2(xv.x, wv0.x, acc[i][0]);
                    acc[i][0] = ffma2(xv.y, wv0.y, acc[i][0]);
                    acc[i][1] = ffma2(xv.x, wv1.x, acc[i][1]);
                    acc[i][1] = ffma2(xv.y, wv1.y, acc[i][1]);
                    acc[i][2] = ffma2(xv.x, wv2.x, acc[i][2]);
                    acc[i][2] = ffma2(xv.y, wv2.y, acc[i][2]);
                }
            }
        }
        // store q,k,v (+bias)
        {
            float bq = bqkv[h * 32 + l];
            float bk = bqkv[256 + h * 32 + l];
            float bv = bqkv[512 + h * 32 + l];
            #pragma unroll
            for (int i = 0; i < 11; ++i) {
                int row = w + 8 * i;
                if (row < NTOK) {
                    sQ[row * 36 + l] = hsum2(acc[i][0]) + bq;
                    sK[row * 36 + l] = hsum2(acc[i][1]) + bk;
                    sV[row * 36 + l] = hsum2(acc[i][2]) + bv;
                }
            }
        }
        __syncthreads();

        // ================= S = scale * q k^T + bias =================
        // thread (w,l): rows {w+8i}, key cols {l, l+32, l+64(<84)}
        {
            u64 sa[11][3];
            #pragma unroll
            for (int i = 0; i < 11; ++i) { sa[i][0] = 0ull; sa[i][1] = 0ull; sa[i][2] = 0ull; }

            #pragma unroll
            for (int d4 = 0; d4 < 8; ++d4) {
                ulonglong2 k0 = *reinterpret_cast<const ulonglong2*>(&sK[ l       * 36 + d4 * 4]);
                ulonglong2 k1 = *reinterpret_cast<const ulonglong2*>(&sK[(l + 32) * 36 + d4 * 4]);
                ulonglong2 k2 = make_ulonglong2(0ull, 0ull);
                if (l < 20)
                    k2 = *reinterpret_cast<const ulonglong2*>(&sK[(l + 64) * 36 + d4 * 4]);
                #pragma unroll
                for (int i = 0; i < 11; ++i) {
                    int row = w + 8 * i;
                    ulonglong2 qv = *reinterpret_cast<const ulonglong2*>(&sQ[row * 36 + d4 * 4]);
                    sa[i][0] = ffma2(qv.x, k0.x, sa[i][0]);
                    sa[i][0] = ffma2(qv.y, k0.y, sa[i][0]);
                    sa[i][1] = ffma2(qv.x, k1.x, sa[i][1]);
                    sa[i][1] = ffma2(qv.y, k1.y, sa[i][1]);
                    sa[i][2] = ffma2(qv.x, k2.x, sa[i][2]);
                    sa[i][2] = ffma2(qv.y, k2.y, sa[i][2]);
                }
            }
            const float* gb = g_bias + h * (NTOK * NTOK);
            #pragma unroll
            for (int i = 0; i < 11; ++i) {
                int row = w + 8 * i;
                if (row < NTOK) {
                    sS[row * 88 + l]      = hsum2(sa[i][0]) * scale + gb[row * 84 + l];
                    sS[row * 88 + l + 32] = hsum2(sa[i][1]) * scale + gb[row * 84 + l + 32];
                    if (l < 20)
                        sS[row * 88 + l + 64] = hsum2(sa[i][2]) * scale + gb[row * 84 + l + 64];
                }
            }
        }
        __syncthreads();

        // ================= softmax (row-wise, one warp per row) =================
        #pragma unroll
        for (int i = 0; i < 11; ++i) {
            int row = w + 8 * i;
            if (row < NTOK) {                 // warp-uniform guard
                float v0 = sS[row * 88 + l];
                float v1 = sS[row * 88 + l + 32];
                float v2 = (l < 20) ? sS[row * 88 + l + 64] : -1e30f;
                float mx = fmaxf(v0, fmaxf(v1, v2));
                #pragma unroll
                for (int off = 16; off; off >>= 1)
                    mx = fmaxf(mx, __shfl_xor_sync(0xffffffffu, mx, off));
                float e0 = __expf(v0 - mx);
                float e1 = __expf(v1 - mx);
                float e2 = (l < 20) ? __expf(v2 - mx) : 0.f;
                float s = e0 + e1 + e2;
                #pragma unroll
                for (int off = 16; off; off >>= 1)
                    s += __shfl_xor_sync(0xffffffffu, s, off);
                float inv = 1.0f / s;
                sS[row * 88 + l]      = e0 * inv;
                sS[row * 88 + l + 32] = e1 * inv;
                if (l < 20) sS[row * 88 + l + 64] = e2 * inv;
            }
        }
        __syncthreads();

        // ================= out_h = P @ V, write to g_attn =================
        {
            float o[11];
            #pragma unroll
            for (int i = 0; i < 11; ++i) o[i] = 0.f;
            #pragma unroll 3
            for (int kq = 0; kq < 21; ++kq) {       // 21*4 = 84 keys
                float v0 = sV[(kq * 4 + 0) * 36 + l];
                float v1 = sV[(kq * 4 + 1) * 36 + l];
                float v2 = sV[(kq * 4 + 2) * 36 + l];
                float v3 = sV[(kq * 4 + 3) * 36 + l];
                #pragma unroll
                for (int i = 0; i < 11; ++i) {
                    int row = w + 8 * i;
                    if (row < NTOK) {
                        float4 p = *reinterpret_cast<const float4*>(&sS[row * 88 + kq * 4]);
                        o[i] += p.x * v0 + p.y * v1 + p.z * v2 + p.w * v3;
                    }
                }
            }
            float* ga = g_attn + (size_t)b * (NTOK * DIM) + h * 32 + l;
            #pragma unroll
            for (int i = 0; i < 11; ++i) {
                int row = w + 8 * i;
                if (row < NTOK) ga[row * 256] = o[i];
            }
        }
        // next head: top-of-kt-loop __syncthreads covers all hazards
    }
}

// ---------------------------------------------------------------------------
// Kernel 3: out = g_attn @ W_proj + b_proj
// smem: xa [88][256] = 22528 floats, wp [128][68] = 8704 floats  -> 124928 B
// ---------------------------------------------------------------------------
__global__ __launch_bounds__(256, 1)
void proj_kernel(const float* __restrict__ Wp,
                 const float* __restrict__ bp,
                 float* __restrict__ out)
{
    extern __shared__ float sm[];
    float* xa = sm;
    float* wp = sm + 22528;
    const int tid = threadIdx.x;
    const int w = tid >> 5, l = tid & 31;
    const int b = blockIdx.x;

    {
        const float4* ag = reinterpret_cast<const float4*>(g_attn + (size_t)b * (NTOK * DIM));
        float4* xa4 = reinterpret_cast<float4*>(xa);
        #pragma unroll
        for (int i = 0; i < 21; ++i)
            xa4[tid + 256 * i] = ag[tid + 256 * i];
        xa4[5376 + tid] = make_float4(0.f, 0.f, 0.f, 0.f);   // zero pad rows 84..87
    }

    for (int half = 0; half < 2; ++half) {
        u64 acc[11][4];
        #pragma unroll
        for (int i = 0; i < 11; ++i)
            #pragma unroll
            for (int m = 0; m < 4; ++m) acc[i][m] = 0ull;

        for (int kt = 0; kt < 4; ++kt) {
            __syncthreads();
            for (int idx = tid; idx < 128 * 64; idx += 256) {
                int j = idx & 127, kk = idx >> 7;
                wp[j * 68 + kk] = Wp[(kt * 64 + kk) * 256 + half * 128 + j];
            }
            __syncthreads();
            #pragma unroll 4
            for (int kk4 = 0; kk4 < 16; ++kk4) {
                ulonglong2 wv[4];
                #pragma unroll
                for (int m = 0; m < 4; ++m)
                    wv[m] = *reinterpret_cast<const ulonglong2*>(&wp[(l + 32 * m) * 68 + kk4 * 4]);
                #pragma unroll
                for (int i = 0; i < 11; ++i) {
                    int row = w + 8 * i;
                    ulonglong2 xv = *reinterpret_cast<const ulonglong2*>(
                        &xa[row * 256 + kt * 64 + kk4 * 4]);
                    #pragma unroll
                    for (int m = 0; m < 4; ++m) {
                        acc[i][m] = ffma2(xv.x, wv[m].x, acc[i][m]);
                        acc[i][m] = ffma2(xv.y, wv[m].y, acc[i][m]);
                    }
                }
            }
        }
        #pragma unroll
        for (int i = 0; i < 11; ++i) {
            int row = w + 8 * i;
            if (row < NTOK) {
                #pragma unroll
                for (int m = 0; m < 4; ++m) {
                    out[((size_t)b * NTOK + row) * 256 + half * 128 + l + 32 * m] =
                        hsum2(acc[i][m]) + bp[half * 128 + l + 32 * m];
                }
            }
        }
    }
}

// ---------------------------------------------------------------------------
extern "C" void kernel_launch(void* const* d_in, const int* in_sizes, int n_in,
                              void* d_out, int out_size)
{
    const float* x     = (const float*)d_in[0];
    const float* Wqkv  = (const float*)d_in[1];
    const float* bqkv  = (const float*)d_in[2];
    const float* Wp    = (const float*)d_in[3];
    const float* bp    = (const float*)d_in[4];
    const float* table = (const float*)d_in[5];
    const int*   ridx  = (const int*)d_in[6];
    float* out = (float*)d_out;

    cudaFuncSetAttribute(attn_kernel, cudaFuncAttributeMaxDynamicSharedMemorySize, 185216);
    cudaFuncSetAttribute(proj_kernel, cudaFuncAttributeMaxDynamicSharedMemorySize, 124928);

    bias_kernel<<<28, 256>>>(table, ridx);
    attn_kernel<<<BATCH, 256, 185216>>>(x, Wqkv, bqkv);
    proj_kernel<<<BATCH, 256, 124928>>>(Wp, bp, out);
}

// round 3
// speedup vs baseline: 2.3220x; 2.3220x over previous
#include <cuda_runtime.h>
#include <cstdint>

// Local Scale Attention — round 3: tf32 mma.sync GEMMs (compute_103-legal) +
// fp32 attention. B=2048, N=84, C=256, H=8, hd=32.
//
//   wprep_kernel : transpose + tf32-round Wqkv->[768][256], Wproj->[256][256]
//   bias_kernel  : gather rel-pos bias -> g_bias[h][q][k]
//   gemm_tf32    : QKV = X @ WqkvT + b   (mma.sync m16n8k8 tf32, 128x128 tiles)
//   attn_kernel  : per-batch fp32 attention (reads g_qkv, writes g_attn)
//   gemm_tf32    : OUT = g_attn @ WprojT + b

#define BATCH 2048
#define NTOK  84
#define DIM   256
#define HEADS 8

typedef unsigned long long u64;

__device__ float g_qkv [(size_t)BATCH * NTOK * 768];   // 528 MB
__device__ float g_attn[(size_t)BATCH * NTOK * DIM];   // 176 MB
__device__ float g_WT  [768 * 256];
__device__ float g_WpT [256 * 256];
__device__ float g_bias[HEADS * NTOK * NTOK];

// ---------------------------------------------------------------------------
// helpers
// ---------------------------------------------------------------------------
__device__ __forceinline__ u64 ffma2(u64 a, u64 b, u64 c) {
    u64 d;
    asm("fma.rn.f32x2 %0, %1, %2, %3;" : "=l"(d) : "l"(a), "l"(b), "l"(c));
    return d;
}
__device__ __forceinline__ float hsum2(u64 v) {
    float lo, hi;
    asm("mov.b64 {%0, %1}, %2;" : "=f"(lo), "=f"(hi) : "l"(v));
    return lo + hi;
}
__device__ __forceinline__ u64 pack2(float lo, float hi) {
    u64 v;
    asm("mov.b64 %0, {%1, %2};" : "=l"(v) : "f"(lo), "f"(hi));
    return v;
}
__device__ __forceinline__ uint32_t smem_u32(const void* p) {
    uint32_t a;
    asm("{ .reg .u64 t; cvta.to.shared.u64 t, %1; cvt.u32.u64 %0, t; }" : "=r"(a) : "l"(p));
    return a;
}
__device__ __forceinline__ void cp_async16(uint32_t dst, const void* src) {
    asm volatile("cp.async.cg.shared.global [%0], [%1], 16;" :: "r"(dst), "l"(src));
}
__device__ __forceinline__ uint32_t tf32u(float x) {
    uint32_t u;
    asm("cvt.rna.tf32.f32 %0, %1;" : "=r"(u) : "f"(x));
    return u;
}
__device__ __forceinline__ float tf32r(float x) { return __uint_as_float(tf32u(x)); }

__device__ __forceinline__ void mma_tf32(float* d, const uint32_t* a, const uint32_t* b) {
    asm volatile(
        "mma.sync.aligned.m16n8k8.row.col.f32.tf32.tf32.f32 "
        "{%0,%1,%2,%3}, {%4,%5,%6,%7}, {%8,%9}, {%0,%1,%2,%3};"
        : "+f"(d[0]), "+f"(d[1]), "+f"(d[2]), "+f"(d[3])
        : "r"(a[0]), "r"(a[1]), "r"(a[2]), "r"(a[3]), "r"(b[0]), "r"(b[1]));
}

// ---------------------------------------------------------------------------
// prep kernels
// ---------------------------------------------------------------------------
__global__ void wprep_kernel(const float* __restrict__ Wqkv, const float* __restrict__ Wp)
{
    int n = blockIdx.x, k = threadIdx.x;
    if (n < 768) g_WT[n * 256 + k] = tf32r(Wqkv[k * 768 + n]);
    else         g_WpT[(n - 768) * 256 + k] = tf32r(Wp[k * 256 + (n - 768)]);
}

__global__ void bias_kernel(const float* __restrict__ table, const int* __restrict__ ridx)
{
    int i = blockIdx.x * blockDim.x + threadIdx.x;
    if (i < NTOK * NTOK) {
        int r = ridx[i];
        #pragma unroll
        for (int h = 0; h < HEADS; ++h)
            g_bias[h * (NTOK * NTOK) + i] = table[r * HEADS + h];
    }
}

// ---------------------------------------------------------------------------
// tf32 GEMM via mma.sync: OUT[m][n] = A[m][:] . BT[n][:] + bias[n]
// grid = (ncols/128, Mrows/128). 256 threads = 8 warps as 4(M) x 2(N),
// each warp computes 32x64. K=256 in 8 chunks of 32, cp.async double-buffered.
// smem (floats): sA[2][128*36], sB[2][128*36]  -> 73728 B, 2 CTA/SM.
// Fragment LDS are conflict-free: stride 36 => bank = (4*row + col) % 32.
// ---------------------------------------------------------------------------
#define GEMM_SMEM 73728

__global__ __launch_bounds__(256, 2)
void gemm_tf32_kernel(const float* __restrict__ A, const float* __restrict__ BT,
                      const float* __restrict__ bias, float* __restrict__ out, int ncols)
{
    extern __shared__ float sm[];
    const uint32_t sb = smem_u32(sm);
    const int tid = threadIdx.x;
    const int w = tid >> 5, lane = tid & 31;
    const int g = lane >> 2, t = lane & 3;       // mma group / thread-in-group
    const int wm = w >> 1, wn = w & 1;           // warp grid 4x2
    const int n0 = blockIdx.x * 128;
    const int m0 = blockIdx.y * 128;

    const float* Ab = A + (size_t)m0 * 256;
    const float* Bb = BT + (size_t)n0 * 256;

    // chunk layout: buf b at floats [b*9216, b*9216+4608) = A, +4608 = B
    auto load_chunk = [&](int kc, int buf) {
        uint32_t ab = sb + buf * (9216 * 4);
        uint32_t bbuf = ab + 4608 * 4;
        int k0 = kc * 32;
        #pragma unroll
        for (int it = 0; it < 4; ++it) {
            int idx = tid + it * 256;            // 1024 float4 per tile
            int r = idx >> 3, c = idx & 7;
            cp_async16(ab + (r * 36 + c * 4) * 4, Ab + r * 256 + k0 + c * 4);
            cp_async16(bbuf + (r * 36 + c * 4) * 4, Bb + r * 256 + k0 + c * 4);
        }
        asm volatile("cp.async.commit_group;" ::: "memory");
    };

    float d[2][8][4];
    #pragma unroll
    for (int i = 0; i < 2; ++i)
        #pragma unroll
        for (int j = 0; j < 8; ++j)
            #pragma unroll
            for (int c = 0; c < 4; ++c) d[i][j][c] = 0.f;

    load_chunk(0, 0);
    load_chunk(1, 1);

    for (int i = 0; i < 8; ++i) {
        int buf = i & 1;
        if (i < 7) asm volatile("cp.async.wait_group 1;" ::: "memory");
        else       asm volatile("cp.async.wait_group 0;" ::: "memory");
        __syncthreads();

        const float* sAb = sm + buf * 9216;
        const float* sBb = sAb + 4608;
        #pragma unroll
        for (int ks = 0; ks < 4; ++ks) {
            uint32_t a[2][4], bf[8][2];
            #pragma unroll
            for (int ii = 0; ii < 2; ++ii) {
                int row = wm * 32 + ii * 16 + g;
                a[ii][0] = tf32u(sAb[ row      * 36 + ks * 8 + t]);
                a[ii][1] = tf32u(sAb[(row + 8) * 36 + ks * 8 + t]);
                a[ii][2] = tf32u(sAb[ row      * 36 + ks * 8 + t + 4]);
                a[ii][3] = tf32u(sAb[(row + 8) * 36 + ks * 8 + t + 4]);
            }
            #pragma unroll
            for (int j = 0; j < 8; ++j) {
                int n = wn * 64 + j * 8 + g;
                bf[j][0] = __float_as_uint(sBb[n * 36 + ks * 8 + t]);
                bf[j][1] = __float_as_uint(sBb[n * 36 + ks * 8 + t + 4]);
            }
            #pragma unroll
            for (int ii = 0; ii < 2; ++ii)
                #pragma unroll
                for (int j = 0; j < 8; ++j)
                    mma_tf32(d[ii][j], a[ii], bf[j]);
        }
        __syncthreads();                          // all warps done with buf
        if (i + 2 < 8) load_chunk(i + 2, buf);
    }

    // epilogue: direct global stores (8B v2, full 32B sectors per lane-quad)
    #pragma unroll
    for (int ii = 0; ii < 2; ++ii) {
        int row = m0 + wm * 32 + ii * 16 + g;
        #pragma unroll
        for (int j = 0; j < 8; ++j) {
            int col = n0 + wn * 64 + j * 8 + 2 * t;
            float b0 = bias[col], b1 = bias[col + 1];
            float2 v0 = make_float2(d[ii][j][0] + b0, d[ii][j][1] + b1);
            float2 v1 = make_float2(d[ii][j][2] + b0, d[ii][j][3] + b1);
            *reinterpret_cast<float2*>(out + (size_t)row * ncols + col) = v0;
            *reinterpret_cast<float2*>(out + (size_t)(row + 8) * ncols + col) = v1;
        }
    }
}

// ---------------------------------------------------------------------------
// fp32 attention. grid=2048, 256 threads, smem 68992 B (3 CTA/SM).
// smem floats: sQ[88][36] sK[88][36] sV[88][36] sS[88][88]
// ---------------------------------------------------------------------------
#define OQ 0
#define OK_ 3168
#define OV 6336
#define OS 9504
#define ATTN_SMEM (17248 * 4)

__global__ __launch_bounds__(256)
void attn_kernel()
{
    extern __shared__ float smf[];
    float* sQ = smf + OQ;
    float* sK = smf + OK_;
    float* sV = smf + OV;
    float* sS = smf + OS;

    const int tid = threadIdx.x;
    const int w = tid >> 5, l = tid & 31;
    const int b = blockIdx.x;
    const float scale = 0.10910894511799618f;   // 84^-0.5

    const float* qkvb = g_qkv + (size_t)b * (NTOK * 768);

    for (int h = 0; h < HEADS; ++h) {
        __syncthreads();   // protect smem reuse from previous head
        // ---- load q (scaled), k, v : 3 x 84 rows x 32 floats ----
        for (int t = tid; t < 2016; t += 256) {
            int s = t / 672, r = t - s * 672;
            int n = r >> 3, c = r & 7;
            float4 v = *reinterpret_cast<const float4*>(
                qkvb + (size_t)n * 768 + s * 256 + h * 32 + c * 4);
            if (s == 0) { v.x *= scale; v.y *= scale; v.z *= scale; v.w *= scale; }
            *reinterpret_cast<float4*>(smf + s * 3168 + n * 36 + c * 4) = v;
        }
        __syncthreads();

        // ---- S = q k^T + bias ----
        {
            u64 sa[11][3];
            #pragma unroll
            for (int i = 0; i < 11; ++i) { sa[i][0] = 0; sa[i][1] = 0; sa[i][2] = 0; }
            #pragma unroll
            for (int d4 = 0; d4 < 8; ++d4) {
                ulonglong2 k0 = *reinterpret_cast<const ulonglong2*>(&sK[ l       * 36 + d4 * 4]);
                ulonglong2 k1 = *reinterpret_cast<const ulonglong2*>(&sK[(l + 32) * 36 + d4 * 4]);
                ulonglong2 k2 = make_ulonglong2(0ull, 0ull);
                if (l < 20)
                    k2 = *reinterpret_cast<const ulonglong2*>(&sK[(l + 64) * 36 + d4 * 4]);
                #pragma unroll
                for (int i = 0; i < 11; ++i) {
                    int row = w + 8 * i;
                    ulonglong2 qv = *reinterpret_cast<const ulonglong2*>(&sQ[row * 36 + d4 * 4]);
                    sa[i][0] = ffma2(qv.x, k0.x, sa[i][0]);
                    sa[i][0] = ffma2(qv.y, k0.y, sa[i][0]);
                    sa[i][1] = ffma2(qv.x, k1.x, sa[i][1]);
                    sa[i][1] = ffma2(qv.y, k1.y, sa[i][1]);
                    sa[i][2] = ffma2(qv.x, k2.x, sa[i][2]);
                    sa[i][2] = ffma2(qv.y, k2.y, sa[i][2]);
                }
            }
            const float* gb = g_bias + h * (NTOK * NTOK);
            #pragma unroll
            for (int i = 0; i < 11; ++i) {
                int row = w + 8 * i;
                if (row < NTOK) {
                    sS[row * 88 + l]      = hsum2(sa[i][0]) + gb[row * 84 + l];
                    sS[row * 88 + l + 32] = hsum2(sa[i][1]) + gb[row * 84 + l + 32];
                    if (l < 20)
                        sS[row * 88 + l + 64] = hsum2(sa[i][2]) + gb[row * 84 + l + 64];
                }
            }
        }
        __syncthreads();

        // ---- softmax ----
        #pragma unroll
        for (int i = 0; i < 11; ++i) {
            int row = w + 8 * i;
            if (row < NTOK) {
                float v0 = sS[row * 88 + l];
                float v1 = sS[row * 88 + l + 32];
                float v2 = (l < 20) ? sS[row * 88 + l + 64] : -1e30f;
                float mx = fmaxf(v0, fmaxf(v1, v2));
                #pragma unroll
                for (int off = 16; off; off >>= 1)
                    mx = fmaxf(mx, __shfl_xor_sync(0xffffffffu, mx, off));
                float e0 = __expf(v0 - mx);
                float e1 = __expf(v1 - mx);
                float e2 = (l < 20) ? __expf(v2 - mx) : 0.f;
                float s = e0 + e1 + e2;
                #pragma unroll
                for (int off = 16; off; off >>= 1)
                    s += __shfl_xor_sync(0xffffffffu, s, off);
                float inv = 1.0f / s;
                sS[row * 88 + l]      = e0 * inv;
                sS[row * 88 + l + 32] = e1 * inv;
                if (l < 20) sS[row * 88 + l + 64] = e2 * inv;
            }
        }
        __syncthreads();

        // ---- out = P @ V ----
        {
            u64 acc2[11];
            #pragma unroll
            for (int i = 0; i < 11; ++i) acc2[i] = 0;
            #pragma unroll 3
            for (int kq = 0; kq < 21; ++kq) {
                float v0 = sV[(kq * 4 + 0) * 36 + l];
                float v1 = sV[(kq * 4 + 1) * 36 + l];
                float v2 = sV[(kq * 4 + 2) * 36 + l];
                float v3 = sV[(kq * 4 + 3) * 36 + l];
                u64 vA = pack2(v0, v1), vB = pack2(v2, v3);
                #pragma unroll
                for (int i = 0; i < 11; ++i) {
                    int row = w + 8 * i;
                    ulonglong2 p = *reinterpret_cast<const ulonglong2*>(&sS[row * 88 + kq * 4]);
                    acc2[i] = ffma2(p.x, vA, acc2[i]);
                    acc2[i] = ffma2(p.y, vB, acc2[i]);
                }
            }
            float* ga = g_attn + (size_t)b * (NTOK * DIM) + h * 32 + l;
            #pragma unroll
            for (int i = 0; i < 11; ++i) {
                int row = w + 8 * i;
                if (row < NTOK) ga[row * 256] = hsum2(acc2[i]);
            }
        }
    }
}

// ---------------------------------------------------------------------------
extern "C" void kernel_launch(void* const* d_in, const int* in_sizes, int n_in,
                              void* d_out, int out_size)
{
    const float* x     = (const float*)d_in[0];
    const float* Wqkv  = (const float*)d_in[1];
    const float* bqkv  = (const float*)d_in[2];
    const float* Wp    = (const float*)d_in[3];
    const float* bp    = (const float*)d_in[4];
    const float* table = (const float*)d_in[5];
    const int*   ridx  = (const int*)d_in[6];
    float* out = (float*)d_out;

    cudaFuncSetAttribute(gemm_tf32_kernel, cudaFuncAttributeMaxDynamicSharedMemorySize, GEMM_SMEM);
    cudaFuncSetAttribute(attn_kernel, cudaFuncAttributeMaxDynamicSharedMemorySize, ATTN_SMEM);

    float* qkv_sc;  cudaGetSymbolAddress((void**)&qkv_sc, g_qkv);
    float* attn_sc; cudaGetSymbolAddress((void**)&attn_sc, g_attn);
    float* wt_sc;   cudaGetSymbolAddress((void**)&wt_sc, g_WT);
    float* wpt_sc;  cudaGetSymbolAddress((void**)&wpt_sc, g_WpT);

    wprep_kernel<<<1024, 256>>>(Wqkv, Wp);
    bias_kernel<<<28, 256>>>(table, ridx);
    gemm_tf32_kernel<<<dim3(6, 1344), 256, GEMM_SMEM>>>(x, wt_sc, bqkv, qkv_sc, 768);
    attn_kernel<<<BATCH, 256, ATTN_SMEM>>>();
    gemm_tf32_kernel<<<dim3(2, 1344), 256, GEMM_SMEM>>>(attn_sc, wpt_sc, bp, out, 256);
}

// round 4
// speedup vs baseline: 2.6811x; 1.1546x over previous
#include <cuda_runtime.h>
#include <cstdint>

// Local Scale Attention — round 4: tf32 mma.sync GEMMs (128x256 CTA tile,
// 512 thr) + fp32 attention at 2 CTA/SM. B=2048, N=84, C=256, H=8, hd=32.

#define BATCH 2048
#define NTOK  84
#define DIM   256
#define HEADS 8

typedef unsigned long long u64;

__device__ float g_qkv [(size_t)BATCH * NTOK * 768];   // 528 MB
__device__ float g_attn[(size_t)BATCH * NTOK * DIM];   // 176 MB
__device__ float g_WT  [768 * 256];
__device__ float g_WpT [256 * 256];
__device__ float g_bias[HEADS * NTOK * NTOK];

// ---------------------------------------------------------------------------
// helpers
// ---------------------------------------------------------------------------
__device__ __forceinline__ u64 ffma2(u64 a, u64 b, u64 c) {
    u64 d;
    asm("fma.rn.f32x2 %0, %1, %2, %3;" : "=l"(d) : "l"(a), "l"(b), "l"(c));
    return d;
}
__device__ __forceinline__ float hsum2(u64 v) {
    float lo, hi;
    asm("mov.b64 {%0, %1}, %2;" : "=f"(lo), "=f"(hi) : "l"(v));
    return lo + hi;
}
__device__ __forceinline__ u64 pack2(float lo, float hi) {
    u64 v;
    asm("mov.b64 %0, {%1, %2};" : "=l"(v) : "f"(lo), "f"(hi));
    return v;
}
__device__ __forceinline__ uint32_t smem_u32(const void* p) {
    uint32_t a;
    asm("{ .reg .u64 t; cvta.to.shared.u64 t, %1; cvt.u32.u64 %0, t; }" : "=r"(a) : "l"(p));
    return a;
}
__device__ __forceinline__ void cp_async16(uint32_t dst, const void* src) {
    asm volatile("cp.async.cg.shared.global [%0], [%1], 16;" :: "r"(dst), "l"(src));
}
__device__ __forceinline__ uint32_t tf32u(float x) {
    uint32_t u;
    asm("cvt.rna.tf32.f32 %0, %1;" : "=r"(u) : "f"(x));
    return u;
}
__device__ __forceinline__ float tf32r(float x) { return __uint_as_float(tf32u(x)); }

__device__ __forceinline__ void mma_tf32(float* d, const uint32_t* a, const uint32_t* b) {
    asm volatile(
        "mma.sync.aligned.m16n8k8.row.col.f32.tf32.tf32.f32 "
        "{%0,%1,%2,%3}, {%4,%5,%6,%7}, {%8,%9}, {%0,%1,%2,%3};"
        : "+f"(d[0]), "+f"(d[1]), "+f"(d[2]), "+f"(d[3])
        : "r"(a[0]), "r"(a[1]), "r"(a[2]), "r"(a[3]), "r"(b[0]), "r"(b[1]));
}

// ---------------------------------------------------------------------------
// prep kernels
// ---------------------------------------------------------------------------
__global__ void wprep_kernel(const float* __restrict__ Wqkv, const float* __restrict__ Wp)
{
    int n = blockIdx.x, k = threadIdx.x;
    if (n < 768) g_WT[n * 256 + k] = tf32r(Wqkv[k * 768 + n]);
    else         g_WpT[(n - 768) * 256 + k] = tf32r(Wp[k * 256 + (n - 768)]);
}

__global__ void bias_kernel(const float* __restrict__ table, const int* __restrict__ ridx)
{
    int i = blockIdx.x * blockDim.x + threadIdx.x;
    if (i < NTOK * NTOK) {
        int r = ridx[i];
        #pragma unroll
        for (int h = 0; h < HEADS; ++h)
            g_bias[h * (NTOK * NTOK) + i] = table[r * HEADS + h];
    }
}

// ---------------------------------------------------------------------------
// tf32 GEMM via mma.sync: OUT[m][n] = A[m][:] . BT[n][:] + bias[n]
// grid = (ncols/256, Mrows/128). 512 threads = 16 warps as 4(M) x 4(N),
// each warp computes 32x64. K=256 in 8 chunks of 32, cp.async double-buffered.
// smem floats: [A0 4608][B0 9216][A1 4608][B1 9216] = 27648 -> 110592 B.
// stride 36 => conflict-free fragment LDS.
// ---------------------------------------------------------------------------
#define GEMM_SMEM 110592

__global__ __launch_bounds__(512, 1)
void gemm_tf32_kernel(const float* __restrict__ A, const float* __restrict__ BT,
                      const float* __restrict__ bias, float* __restrict__ out, int ncols)
{
    extern __shared__ float sm[];
    const uint32_t sb = smem_u32(sm);
    const int tid = threadIdx.x;
    const int w = tid >> 5, lane = tid & 31;
    const int g = lane >> 2, t = lane & 3;       // mma group / thread-in-group
    const int wm = w >> 2, wn = w & 3;           // warp grid 4x4
    const int n0 = blockIdx.x * 256;
    const int m0 = blockIdx.y * 128;

    const float* Ab = A + (size_t)m0 * 256;
    const float* Bb = BT + (size_t)n0 * 256;

    auto load_chunk = [&](int kc, int buf) {
        uint32_t ab = sb + buf * (13824 * 4);
        uint32_t bbuf = ab + 4608 * 4;
        int k0 = kc * 32;
        #pragma unroll
        for (int it = 0; it < 2; ++it) {          // A: 1024 float4
            int idx = tid + it * 512;
            int r = idx >> 3, c = idx & 7;
            cp_async16(ab + (r * 36 + c * 4) * 4, Ab + r * 256 + k0 + c * 4);
        }
        #pragma unroll
        for (int it = 0; it < 4; ++it) {          // B: 2048 float4
            int idx = tid + it * 512;
            int r = idx >> 3, c = idx & 7;
            cp_async16(bbuf + (r * 36 + c * 4) * 4, Bb + r * 256 + k0 + c * 4);
        }
        asm volatile("cp.async.commit_group;" ::: "memory");
    };

    float d[2][8][4];
    #pragma unroll
    for (int i = 0; i < 2; ++i)
        #pragma unroll
        for (int j = 0; j < 8; ++j)
            #pragma unroll
            for (int c = 0; c < 4; ++c) d[i][j][c] = 0.f;

    load_chunk(0, 0);
    load_chunk(1, 1);

    for (int i = 0; i < 8; ++i) {
        int buf = i & 1;
        if (i < 7) asm volatile("cp.async.wait_group 1;" ::: "memory");
        else       asm volatile("cp.async.wait_group 0;" ::: "memory");
        __syncthreads();

        const float* sAb = sm + buf * 13824;
        const float* sBb = sAb + 4608;
        #pragma unroll
        for (int ks = 0; ks < 4; ++ks) {
            uint32_t a[2][4], bf[8][2];
            #pragma unroll
            for (int ii = 0; ii < 2; ++ii) {
                int row = wm * 32 + ii * 16 + g;
                a[ii][0] = tf32u(sAb[ row      * 36 + ks * 8 + t]);
                a[ii][1] = tf32u(sAb[(row + 8) * 36 + ks * 8 + t]);
                a[ii][2] = tf32u(sAb[ row      * 36 + ks * 8 + t + 4]);
                a[ii][3] = tf32u(sAb[(row + 8) * 36 + ks * 8 + t + 4]);
            }
            #pragma unroll
            for (int j = 0; j < 8; ++j) {
                int n = wn * 64 + j * 8 + g;
                bf[j][0] = __float_as_uint(sBb[n * 36 + ks * 8 + t]);
                bf[j][1] = __float_as_uint(sBb[n * 36 + ks * 8 + t + 4]);
            }
            #pragma unroll
            for (int ii = 0; ii < 2; ++ii)
                #pragma unroll
                for (int j = 0; j < 8; ++j)
                    mma_tf32(d[ii][j], a[ii], bf[j]);
        }
        __syncthreads();
        if (i + 2 < 8) load_chunk(i + 2, buf);
    }

    // epilogue: direct global stores
    #pragma unroll
    for (int ii = 0; ii < 2; ++ii) {
        int row = m0 + wm * 32 + ii * 16 + g;
        #pragma unroll
        for (int j = 0; j < 8; ++j) {
            int col = n0 + wn * 64 + j * 8 + 2 * t;
            float b0 = bias[col], b1 = bias[col + 1];
            float2 v0 = make_float2(d[ii][j][0] + b0, d[ii][j][1] + b1);
            float2 v1 = make_float2(d[ii][j][2] + b0, d[ii][j][3] + b1);
            *reinterpret_cast<float2*>(out + (size_t)row * ncols + col) = v0;
            *reinterpret_cast<float2*>(out + (size_t)(row + 8) * ncols + col) = v1;
        }
    }
}

// ---------------------------------------------------------------------------
// fp32 attention. grid=2048, 256 threads, 2 CTA/SM (regs capped at 128).
// smem floats: sQ[88][36] sK[88][36] sV[88][36] sS[88][88]
// ---------------------------------------------------------------------------
#define OQ 0
#define OK_ 3168
#define OV 6336
#define OS 9504
#define ATTN_SMEM (17248 * 4)

__global__ __launch_bounds__(256, 2)
void attn_kernel()
{
    extern __shared__ float smf[];
    float* sQ = smf + OQ;
    float* sK = smf + OK_;
    float* sV = smf + OV;
    float* sS = smf + OS;

    const int tid = threadIdx.x;
    const int w = tid >> 5, l = tid & 31;
    const int b = blockIdx.x;
    const float scale = 0.10910894511799618f;   // 84^-0.5

    const float* qkvb = g_qkv + (size_t)b * (NTOK * 768);

    for (int h = 0; h < HEADS; ++h) {
        __syncthreads();   // protect smem reuse from previous head
        // ---- load q (scaled), k, v : 3 x 84 rows x 32 floats ----
        for (int t = tid; t < 2016; t += 256) {
            int s = t / 672, r = t - s * 672;
            int n = r >> 3, c = r & 7;
            float4 v = *reinterpret_cast<const float4*>(
                qkvb + (size_t)n * 768 + s * 256 + h * 32 + c * 4);
            if (s == 0) { v.x *= scale; v.y *= scale; v.z *= scale; v.w *= scale; }
            *reinterpret_cast<float4*>(smf + s * 3168 + n * 36 + c * 4) = v;
        }
        __syncthreads();

        // ---- S = q k^T + bias ----
        {
            u64 sa[11][3];
            #pragma unroll
            for (int i = 0; i < 11; ++i) { sa[i][0] = 0; sa[i][1] = 0; sa[i][2] = 0; }
            #pragma unroll
            for (int d4 = 0; d4 < 8; ++d4) {
                ulonglong2 k0 = *reinterpret_cast<const ulonglong2*>(&sK[ l       * 36 + d4 * 4]);
                ulonglong2 k1 = *reinterpret_cast<const ulonglong2*>(&sK[(l + 32) * 36 + d4 * 4]);
                ulonglong2 k2 = make_ulonglong2(0ull, 0ull);
                if (l < 20)
                    k2 = *reinterpret_cast<const ulonglong2*>(&sK[(l + 64) * 36 + d4 * 4]);
                #pragma unroll
                for (int i = 0; i < 11; ++i) {
                    int row = w + 8 * i;
                    ulonglong2 qv = *reinterpret_cast<const ulonglong2*>(&sQ[row * 36 + d4 * 4]);
                    sa[i][0] = ffma2(qv.x, k0.x, sa[i][0]);
                    sa[i][0] = ffma2(qv.y, k0.y, sa[i][0]);
                    sa[i][1] = ffma2(qv.x, k1.x, sa[i][1]);
                    sa[i][1] = ffma2(qv.y, k1.y, sa[i][1]);
                    sa[i][2] = ffma2(qv.x, k2.x, sa[i][2]);
                    sa[i][2] = ffma2(qv.y, k2.y, sa[i][2]);
                }
            }
            const float* gb = g_bias + h * (NTOK * NTOK);
            #pragma unroll
            for (int i = 0; i < 11; ++i) {
                int row = w + 8 * i;
                if (row < NTOK) {
                    sS[row * 88 + l]      = hsum2(sa[i][0]) + gb[row * 84 + l];
                    sS[row * 88 + l + 32] = hsum2(sa[i][1]) + gb[row * 84 + l + 32];
                    if (l < 20)
                        sS[row * 88 + l + 64] = hsum2(sa[i][2]) + gb[row * 84 + l + 64];
                }
            }
        }
        __syncthreads();

        // ---- softmax ----
        #pragma unroll
        for (int i = 0; i < 11; ++i) {
            int row = w + 8 * i;
            if (row < NTOK) {
                float v0 = sS[row * 88 + l];
                float v1 = sS[row * 88 + l + 32];
                float v2 = (l < 20) ? sS[row * 88 + l + 64] : -1e30f;
                float mx = fmaxf(v0, fmaxf(v1, v2));
                #pragma unroll
                for (int off = 16; off; off >>= 1)
                    mx = fmaxf(mx, __shfl_xor_sync(0xffffffffu, mx, off));
                float e0 = __expf(v0 - mx);
                float e1 = __expf(v1 - mx);
                float e2 = (l < 20) ? __expf(v2 - mx) : 0.f;
                float s = e0 + e1 + e2;
                #pragma unroll
                for (int off = 16; off; off >>= 1)
                    s += __shfl_xor_sync(0xffffffffu, s, off);
                float inv = 1.0f / s;
                sS[row * 88 + l]      = e0 * inv;
                sS[row * 88 + l + 32] = e1 * inv;
                if (l < 20) sS[row * 88 + l + 64] = e2 * inv;
            }
        }
        __syncthreads();

        // ---- out = P @ V ----
        {
            u64 acc2[11];
            #pragma unroll
            for (int i = 0; i < 11; ++i) acc2[i] = 0;
            #pragma unroll 3
            for (int kq = 0; kq < 21; ++kq) {
                float v0 = sV[(kq * 4 + 0) * 36 + l];
                float v1 = sV[(kq * 4 + 1) * 36 + l];
                float v2 = sV[(kq * 4 + 2) * 36 + l];
                float v3 = sV[(kq * 4 + 3) * 36 + l];
                u64 vA = pack2(v0, v1), vB = pack2(v2, v3);
                #pragma unroll
                for (int i = 0; i < 11; ++i) {
                    int row = w + 8 * i;
                    ulonglong2 p = *reinterpret_cast<const ulonglong2*>(&sS[row * 88 + kq * 4]);
                    acc2[i] = ffma2(p.x, vA, acc2[i]);
                    acc2[i] = ffma2(p.y, vB, acc2[i]);
                }
            }
            float* ga = g_attn + (size_t)b * (NTOK * DIM) + h * 32 + l;
            #pragma unroll
            for (int i = 0; i < 11; ++i) {
                int row = w + 8 * i;
                if (row < NTOK) ga[row * 256] = hsum2(acc2[i]);
            }
        }
    }
}

// ---------------------------------------------------------------------------
extern "C" void kernel_launch(void* const* d_in, const int* in_sizes, int n_in,
                              void* d_out, int out_size)
{
    const float* x     = (const float*)d_in[0];
    const float* Wqkv  = (const float*)d_in[1];
    const float* bqkv  = (const float*)d_in[2];
    const float* Wp    = (const float*)d_in[3];
    const float* bp    = (const float*)d_in[4];
    const float* table = (const float*)d_in[5];
    const int*   ridx  = (const int*)d_in[6];
    float* out = (float*)d_out;

    cudaFuncSetAttribute(gemm_tf32_kernel, cudaFuncAttributeMaxDynamicSharedMemorySize, GEMM_SMEM);
    cudaFuncSetAttribute(attn_kernel, cudaFuncAttributeMaxDynamicSharedMemorySize, ATTN_SMEM);

    float* qkv_sc;  cudaGetSymbolAddress((void**)&qkv_sc, g_qkv);
    float* attn_sc; cudaGetSymbolAddress((void**)&attn_sc, g_attn);
    float* wt_sc;   cudaGetSymbolAddress((void**)&wt_sc, g_WT);
    float* wpt_sc;  cudaGetSymbolAddress((void**)&wpt_sc, g_WpT);

    wprep_kernel<<<1024, 256>>>(Wqkv, Wp);
    bias_kernel<<<28, 256>>>(table, ridx);
    gemm_tf32_kernel<<<dim3(3, 1344), 512, GEMM_SMEM>>>(x, wt_sc, bqkv, qkv_sc, 768);
    attn_kernel<<<BATCH, 256, ATTN_SMEM>>>();
    gemm_tf32_kernel<<<dim3(1, 1344), 512, GEMM_SMEM>>>(attn_sc, wpt_sc, bp, out, 256);
}